// round 4
// baseline (speedup 1.0000x reference)
#include <cuda_runtime.h>
#include <stdint.h>

#define RNODES 256
#define LUT_WORDS 8192        // 2^18 / 32
#define NSTEP 512
#define NSAMP 512
#define NIN 32
#define NOUT 10
#define NGROUP 128            // 2-bit groups of k
#define TAB_ENTRIES (NGROUP * 3 * 32)   // uint4 entries: 12288 (196,608 B)
// SMEM u32: pad 128 | tab 49152 | xw 2048 | bits 1024 = 52352 u32 = 209,408 B
#define SMEM_U32 52352
#define SMEM_BYTES (SMEM_U32 * 4)

// Static device scratch (allocation-free rule).
__device__ uint32_t g_lutbits[RNODES * LUT_WORDS];  // 8 MB bit-packed LUT
__device__ uint4    g_tab4[TAB_ENTRIES];            // combo table, LDS.128 layout
__device__ uint32_t g_xpack[NSAMP * NSTEP];         // per (m,s): 32 input bits
__device__ int      g_inv[RNODES];                  // node -> input slot, or -1
__device__ int      g_init[RNODES];                 // initial state bits
__device__ int      g_mode;                         // bool enc: 0=int32 1=uint8 2=float32

__device__ __forceinline__ int read_bool(const void* p, long i, int mode) {
    if (mode == 0) return ((const int*)p)[i] != 0;
    if (mode == 1) return ((const unsigned char*)p)[i] != 0;
    return ((const float*)p)[i] != 0.0f;
}

__global__ void detect_kernel(const uint32_t* __restrict__ xw) {
    if (threadIdx.x == 0 && blockIdx.x == 0) {
        int mode = 0;
        for (int i = 0; i < 1024; i++) {
            uint32_t v = xw[i];
            if (v == 0x3f800000u) { mode = 2; break; }
            if (v > 1u) mode = 1;
        }
        g_mode = mode;
    }
}

__global__ void pack_lut_kernel(const int* __restrict__ lut) {
    int w = blockIdx.x * blockDim.x + threadIdx.x;
    if (w >= RNODES * LUT_WORDS) return;
    const int* src = lut + (size_t)w * 32;
    uint32_t v = 0;
#pragma unroll
    for (int b = 0; b < 32; b++) v |= ((uint32_t)(src[b] & 1)) << b;
    g_lutbits[w] = v;
}

__global__ void pack_x_kernel(const void* __restrict__ x) {
    int w = blockIdx.x * blockDim.x + threadIdx.x;   // (m*NSTEP + s)
    if (w >= NSAMP * NSTEP) return;
    int mode = g_mode;
    long base = (long)w * 32;
    uint32_t v = 0;
#pragma unroll
    for (int q = 0; q < 32; q++)
        v |= ((uint32_t)read_bool(x, base + q, mode)) << q;
    g_xpack[w] = v;
}

__global__ void prep_misc_kernel(const int* __restrict__ input_nodes,
                                 const void* __restrict__ init_res) {
    int i = blockIdx.x * blockDim.x + threadIdx.x;
    if (i >= RNODES) return;
    int mode = g_mode;
    int inv = -1;
#pragma unroll
    for (int q = 0; q < NIN; q++)
        if (input_nodes[q] == i) inv = q;
    g_inv[i] = inv;
    g_init[i] = read_bool(init_res, i, mode);
}

// Combo table entry (g, c-1, lane): uint4 packing 8 node sums (u16 each):
//   .x = node(l)     | node(l+128) << 16
//   .y = node(l+32)  | node(l+160) << 16
//   .z = node(l+64)  | node(l+192) << 16
//   .w = node(l+96)  | node(l+224) << 16
// where node(n) = sum over combo bits: (c&1)?p[2g]*W[n,2g] + (c&2)?p[2g+1]*W[n,2g+1]
__global__ void prep_tab_kernel(const void* __restrict__ W,
                                const int* __restrict__ primes) {
    int i = blockIdx.x * blockDim.x + threadIdx.x;
    if (i >= TAB_ENTRIES) return;
    int l   = i & 31;
    int cm1 = (i >> 5) % 3;
    int g   = i / 96;
    int c   = cm1 + 1;
    int k0 = 2 * g, k1 = 2 * g + 1;
    int mode = g_mode;
    uint32_t p0 = (c & 1) ? (uint32_t)primes[k0] : 0u;
    uint32_t p1 = (c & 2) ? (uint32_t)primes[k1] : 0u;
    uint32_t v[8];
#pragma unroll
    for (int q = 0; q < 8; q++) {
        int node = l + q * 32;
        uint32_t s = 0;
        if (read_bool(W, (long)node * RNODES + k0, mode)) s += p0;
        if (read_bool(W, (long)node * RNODES + k1, mode)) s += p1;
        v[q] = s;
    }
    uint4 e;
    e.x = v[0] | (v[4] << 16);
    e.y = v[1] | (v[5] << 16);
    e.z = v[2] | (v[6] << 16);
    e.w = v[3] | (v[7] << 16);
    g_tab4[i] = e;
}

// 128 CTAs x 128 threads (4 warps). Warp = one sample chain, fully
// self-contained: lane l owns nodes 32q+l (q=0..7); state masks come from
// 8 ballots; NO barriers inside the step loop.
__global__ void __launch_bounds__(128, 1)
reservoir_kernel(const float* __restrict__ roW,
                 const float* __restrict__ rob,
                 float* __restrict__ out) {
    extern __shared__ uint32_t sm[];
    uint4*    sh_pad  = (uint4*)sm;               // 32 uint4 zero pad (c==0 underflow)
    uint4*    sh_tab  = (uint4*)sm + 32;          // 12288 uint4 (192 KB)
    uint32_t* sh_xw   = sm + 128 + TAB_ENTRIES * 4;   // 2048 u32
    float*    sh_bits = (float*)(sh_xw + 2048);   // 1024 floats

    const int tid  = threadIdx.x;
    const int wid  = tid >> 5;        // sample in CTA (0..3)
    const int l    = tid & 31;

    // Stage table + pad + packed x
    if (tid < 32) sh_pad[tid] = make_uint4(0, 0, 0, 0);
    for (int i = tid; i < TAB_ENTRIES; i += 128)
        sh_tab[i] = g_tab4[i];
    for (int i = tid; i < 2048; i += 128)
        sh_xw[i] = g_xpack[blockIdx.x * 2048 + i];

    // Per-lane node metadata (nodes 32q + l)
    int inv[8];
    unsigned b[8];
#pragma unroll
    for (int q = 0; q < 8; q++) {
        inv[q] = g_inv[32 * q + l];
        b[q]   = (unsigned)g_init[32 * q + l];
    }

    __syncthreads();

    const uint32_t* xs   = sh_xw + wid * NSTEP;
    const uint4*   tab_l = sh_tab + l;            // lane-offset base

#pragma unroll 1
    for (int s = 0; s < NSTEP; s++) {
        // 1) input override + 2) in-register state masks via ballots
        uint32_t xw = xs[s];
        uint32_t wv[8];
#pragma unroll
        for (int q = 0; q < 8; q++) {
            unsigned a = (inv[q] >= 0) ? ((xw >> inv[q]) & 1u) : b[q];
            wv[q] = __ballot_sync(0xffffffffu, a);
        }

        // 3) combo-table sums: 8 nodes per lane, packed u16 accumulation
        uint32_t ilo[4] = {0, 0, 0, 0};   // nodes 32j+l
        uint32_t ihi[4] = {0, 0, 0, 0};   // nodes 32(j+4)+l
#pragma unroll
        for (int wi = 0; wi < 8; wi++) {
            uint32_t word = wv[wi];
            uint32_t a0 = 0, a1 = 0, a2 = 0, a3 = 0;
#pragma unroll
            for (int q = 0; q < 16; q++) {
                uint32_t c = (word >> (2 * q)) & 3u;
                int g = wi * 16 + q;
                // c==0 underflows into the zero pad (adds masked anyway)
                uint4 e = tab_l[(g * 3 - 1 + (int)c) * 32];
                if (c) {
                    a0 = __vadd2(a0, e.x);
                    a1 = __vadd2(a1, e.y);
                    a2 = __vadd2(a2, e.z);
                    a3 = __vadd2(a3, e.w);
                }
            }
            ilo[0] += a0 & 0xFFFFu;  ihi[0] += a0 >> 16;
            ilo[1] += a1 & 0xFFFFu;  ihi[1] += a1 >> 16;
            ilo[2] += a2 & 0xFFFFu;  ihi[2] += a2 >> 16;
            ilo[3] += a3 & 0xFFFFu;  ihi[3] += a3 >> 16;
        }

        // 4) bit-packed LUT gather (8 MB, L2-resident); 8 independent LDGs
        uint32_t lbase = (uint32_t)l << 13;
#pragma unroll
        for (int j = 0; j < 4; j++) {
            uint32_t v0 = ilo[j], v1 = ihi[j];
            uint32_t w0 = g_lutbits[lbase + ((uint32_t)j << 18)       + (v0 >> 5)];
            uint32_t w1 = g_lutbits[lbase + ((uint32_t)(j + 4) << 18) + (v1 >> 5)];
            b[j]     = (w0 >> (v0 & 31u)) & 1u;
            b[j + 4] = (w1 >> (v1 & 31u)) & 1u;
        }
    }

    // Readout
    float* bits = sh_bits + wid * 256;
#pragma unroll
    for (int q = 0; q < 8; q++)
        bits[32 * q + l] = (float)b[q];
    __syncthreads();

    if (tid < 4 * NOUT) {
        int so = tid / NOUT;
        int o  = tid % NOUT;
        float acc = rob[o];
        const float* wrow = roW + o * RNODES;
        const float* bb = sh_bits + so * 256;
#pragma unroll 8
        for (int j = 0; j < RNODES; j++)
            acc += bb[j] * wrow[j];
        out[(blockIdx.x * 4 + so) * NOUT + o] = acc;
    }
}

extern "C" void kernel_launch(void* const* d_in, const int* in_sizes, int n_in,
                              void* d_out, int out_size) {
    const void* x       = d_in[0];                   // bool [512,512,4,8] (dtype-detected)
    const int*  innod   = (const int*)d_in[1];       // int32 [32]
    const int*  lut     = (const int*)d_in[2];       // int32 [256, 262144]
    const void* W       = d_in[3];                   // bool [256,256]
    const int*  primes  = (const int*)d_in[4];       // int32 [256]
    const void* initres = d_in[5];                   // bool [256]
    const float* roW    = (const float*)d_in[6];     // f32 [10,256]
    const float* rob    = (const float*)d_in[7];     // f32 [10]
    float* out = (float*)d_out;                      // f32 [512,10]

    cudaFuncSetAttribute(reservoir_kernel,
                         cudaFuncAttributeMaxDynamicSharedMemorySize, SMEM_BYTES);

    detect_kernel<<<1, 32>>>((const uint32_t*)x);
    pack_lut_kernel<<<(RNODES * LUT_WORDS + 255) / 256, 256>>>(lut);
    pack_x_kernel<<<(NSAMP * NSTEP + 255) / 256, 256>>>(x);
    prep_misc_kernel<<<1, 256>>>(innod, initres);
    prep_tab_kernel<<<(TAB_ENTRIES + 255) / 256, 256>>>(W, primes);
    reservoir_kernel<<<128, 128, SMEM_BYTES>>>(roW, rob, out);
}

// round 5
// speedup vs baseline: 3.8141x; 3.8141x over previous
#include <cuda_runtime.h>
#include <stdint.h>

#define RNODES 256
#define LUT_WORDS 8192        // 2^18 / 32
#define NSTEP 512
#define NSAMP 512
#define NIN 32
#define NOUT 10
#define NG8 32                // 8-bit groups of k
#define TAB8_ENTRIES (NG8 * 256 * 128)   // u32 per node-pair: 4 MB
// SMEM: xw 512 | rbuf 16 | bits 256 = 784 u32
#define SMEM_BYTES (784 * 4)

// Static device scratch (allocation-free rule).
__device__ uint32_t g_lutbits[RNODES * LUT_WORDS];  // 8 MB bit-packed LUT (L2)
__device__ uint32_t g_tab8[TAB8_ENTRIES];           // 4 MB byte-group combo table (L2)
__device__ uint32_t g_xpack[NSAMP * NSTEP];         // per (m,s): 32 input bits
__device__ int      g_inv[RNODES];                  // node -> input slot, or -1
__device__ int      g_init[RNODES];                 // initial state bits
__device__ int      g_mode;                         // bool enc: 0=int32 1=uint8 2=float32

__device__ __forceinline__ int read_bool(const void* p, long i, int mode) {
    if (mode == 0) return ((const int*)p)[i] != 0;
    if (mode == 1) return ((const unsigned char*)p)[i] != 0;
    return ((const float*)p)[i] != 0.0f;
}

__global__ void detect_kernel(const uint32_t* __restrict__ xw) {
    if (threadIdx.x == 0 && blockIdx.x == 0) {
        int mode = 0;
        for (int i = 0; i < 1024; i++) {
            uint32_t v = xw[i];
            if (v == 0x3f800000u) { mode = 2; break; }
            if (v > 1u) mode = 1;
        }
        g_mode = mode;
    }
}

__global__ void pack_lut_kernel(const int* __restrict__ lut) {
    int w = blockIdx.x * blockDim.x + threadIdx.x;
    if (w >= RNODES * LUT_WORDS) return;
    const int* src = lut + (size_t)w * 32;
    uint32_t v = 0;
#pragma unroll
    for (int b = 0; b < 32; b++) v |= ((uint32_t)(src[b] & 1)) << b;
    g_lutbits[w] = v;
}

__global__ void pack_x_kernel(const void* __restrict__ x) {
    int w = blockIdx.x * blockDim.x + threadIdx.x;   // (m*NSTEP + s)
    if (w >= NSAMP * NSTEP) return;
    int mode = g_mode;
    long base = (long)w * 32;
    uint32_t v = 0;
#pragma unroll
    for (int q = 0; q < 32; q++)
        v |= ((uint32_t)read_bool(x, base + q, mode)) << q;
    g_xpack[w] = v;
}

__global__ void prep_misc_kernel(const int* __restrict__ input_nodes,
                                 const void* __restrict__ init_res) {
    int i = blockIdx.x * blockDim.x + threadIdx.x;
    if (i >= RNODES) return;
    int mode = g_mode;
    int inv = -1;
#pragma unroll
    for (int q = 0; q < NIN; q++)
        if (input_nodes[q] == i) inv = q;
    g_inv[i] = inv;
    g_init[i] = read_bool(init_res, i, mode);
}

// Byte-group combo table: entry (g, c, t) = u16 pair:
//   lo = sum_{j: c bit j} primes[8g+j]*W[t, 8g+j]
//   hi = same for node t+128
__global__ void prep_tab8_kernel(const void* __restrict__ W,
                                 const int* __restrict__ primes) {
    int i = blockIdx.x * blockDim.x + threadIdx.x;
    if (i >= TAB8_ENTRIES) return;
    int t = i & 127;
    int c = (i >> 7) & 255;
    int g = i >> 15;
    int mode = g_mode;
    uint32_t lo = 0, hi = 0;
#pragma unroll
    for (int j = 0; j < 8; j++) {
        if (c & (1 << j)) {
            int k = 8 * g + j;
            uint32_t p = (uint32_t)primes[k];
            if (read_bool(W, (long)t * RNODES + k, mode))         lo += p;
            if (read_bool(W, (long)(t + 128) * RNODES + k, mode)) hi += p;
        }
    }
    g_tab8[i] = lo | (hi << 16);
}

// 512 CTAs x 128 threads. CTA = one sample; thread t owns nodes t and t+128
// (packed u16 accumulation). Mask exchange: ballots + SMEM + 1 syncthreads.
__global__ void __launch_bounds__(128, 4)
reservoir_kernel(const float* __restrict__ roW,
                 const float* __restrict__ rob,
                 float* __restrict__ out) {
    __shared__ uint32_t sh_xw[NSTEP];
    __shared__ uint32_t sh_r[16];       // 2 bufs * 8 mask words
    __shared__ float    sh_bits[RNODES];

    const int t    = threadIdx.x;       // 0..127
    const int w    = t >> 5;            // warp 0..3
    const int lane = t & 31;
    const int sid  = blockIdx.x;        // sample

    for (int i = t; i < NSTEP; i += 128)
        sh_xw[i] = g_xpack[sid * NSTEP + i];

    const int inv0 = g_inv[t];
    const int inv1 = g_inv[t + 128];
    unsigned b0 = (unsigned)g_init[t];
    unsigned b1 = (unsigned)g_init[t + 128];

    __syncthreads();

    for (int s = 0; s < NSTEP; s++) {
        // 1) input override (before the matvec, as in the reference)
        uint32_t xw = sh_xw[s];
        unsigned a0 = (inv0 >= 0) ? ((xw >> inv0) & 1u) : b0;
        unsigned a1 = (inv1 >= 0) ? ((xw >> inv1) & 1u) : b1;

        // 2) state bitmask words: warp w -> words w and w+4
        unsigned m0 = __ballot_sync(0xffffffffu, a0);
        unsigned m1 = __ballot_sync(0xffffffffu, a1);
        uint32_t* rb = sh_r + (s & 1) * 8;
        if (lane == 0) { rb[w] = m0; rb[w + 4] = m1; }
        __syncthreads();

        uint4 ra  = *(const uint4*)(rb);
        uint4 rb4 = *(const uint4*)(rb + 4);
        uint32_t wv[8] = {ra.x, ra.y, ra.z, ra.w, rb4.x, rb4.y, rb4.z, rb4.w};

        // 3) byte-group combo sums from the 4 MB L2 table:
        //    32 independent LDG.32, unconditional packed adds.
        uint32_t i0 = 0, i1 = 0;
#pragma unroll
        for (int wi = 0; wi < 8; wi++) {
            uint32_t word = wv[wi];
            uint32_t acc = 0;   // packed u16 pair; per-word max < 65536
#pragma unroll
            for (int qb = 0; qb < 4; qb++) {
                uint32_t c = (word >> (8 * qb)) & 0xFFu;
                // entry index = ((g*256 + c)*128 + t), g = 4*wi + qb
                acc = __vadd2(acc,
                    __ldg(&g_tab8[(((wi * 4 + qb) << 8) + c) * 128 + t]));
            }
            i0 += acc & 0xFFFFu;
            i1 += acc >> 16;
        }

        // 4) bit-packed LUT gather (8 MB, L2-resident)
        uint32_t w0 = __ldg(&g_lutbits[((uint32_t)t << 13)         + (i0 >> 5)]);
        uint32_t w1 = __ldg(&g_lutbits[((uint32_t)(t + 128) << 13) + (i1 >> 5)]);
        b0 = (w0 >> (i0 & 31u)) & 1u;
        b1 = (w1 >> (i1 & 31u)) & 1u;
    }

    // Readout: out[m, o] = sum_j rf[m,j] * roW[o,j] + rob[o]
    sh_bits[t]       = (float)b0;
    sh_bits[t + 128] = (float)b1;
    __syncthreads();

    if (t < NOUT) {
        float acc = rob[t];
        const float* wrow = roW + t * RNODES;
#pragma unroll 8
        for (int j = 0; j < RNODES; j++)
            acc += sh_bits[j] * wrow[j];
        out[sid * NOUT + t] = acc;
    }
}

extern "C" void kernel_launch(void* const* d_in, const int* in_sizes, int n_in,
                              void* d_out, int out_size) {
    const void* x       = d_in[0];                   // bool [512,512,4,8] (dtype-detected)
    const int*  innod   = (const int*)d_in[1];       // int32 [32]
    const int*  lut     = (const int*)d_in[2];       // int32 [256, 262144]
    const void* W       = d_in[3];                   // bool [256,256]
    const int*  primes  = (const int*)d_in[4];       // int32 [256]
    const void* initres = d_in[5];                   // bool [256]
    const float* roW    = (const float*)d_in[6];     // f32 [10,256]
    const float* rob    = (const float*)d_in[7];     // f32 [10]
    float* out = (float*)d_out;                      // f32 [512,10]

    detect_kernel<<<1, 32>>>((const uint32_t*)x);
    pack_lut_kernel<<<(RNODES * LUT_WORDS + 255) / 256, 256>>>(lut);
    pack_x_kernel<<<(NSAMP * NSTEP + 255) / 256, 256>>>(x);
    prep_misc_kernel<<<1, 256>>>(innod, initres);
    prep_tab8_kernel<<<(TAB8_ENTRIES + 255) / 256, 256>>>(W, primes);
    reservoir_kernel<<<NSAMP, 128>>>(roW, rob, out);
}

// round 6
// speedup vs baseline: 4.4508x; 1.1669x over previous
#include <cuda_runtime.h>
#include <stdint.h>

#define RNODES 256
#define LUT_WORDS 8192            // 2^18 / 32
#define NSTEP 512
#define NSAMP 512
#define NIN 32
#define NOUT 10

// 6-bit half-groups: 43 groups (last covers k=252..255, rest zero)
#define NH6 43
#define TAB6_ROWS (NH6 * 64)
// 12-bit groups: 21 full (g=0..20) + one 4-bit tail group
#define NG12 21
#define TAB12_ROWS (NG12 * 4096 + 16)   // 86032 rows
#define TAB12_TAIL (NG12 * 4096)        // row base of tail group

// Static device scratch (allocation-free rule).
__device__ uint32_t g_lutbits[RNODES * LUT_WORDS];     // 8 MB bit-packed LUT (L2)
__device__ uint32_t g_tab6[TAB6_ROWS * 128];           // 1.4 MB half tables
__device__ uint32_t g_tab12[TAB12_ROWS * 128];         // 44 MB combo table (L2)
__device__ uint32_t g_xpack[NSAMP * NSTEP];            // per (m,s): 32 input bits
__device__ int      g_inv[RNODES];                     // node -> input slot, or -1
__device__ int      g_init[RNODES];                    // initial state bits
__device__ int      g_mode;                            // bool enc: 0=i32 1=u8 2=f32

__device__ __forceinline__ int read_bool(const void* p, long i, int mode) {
    if (mode == 0) return ((const int*)p)[i] != 0;
    if (mode == 1) return ((const unsigned char*)p)[i] != 0;
    return ((const float*)p)[i] != 0.0f;
}

__global__ void detect_kernel(const uint32_t* __restrict__ xw) {
    if (threadIdx.x == 0 && blockIdx.x == 0) {
        int mode = 0;
        for (int i = 0; i < 1024; i++) {
            uint32_t v = xw[i];
            if (v == 0x3f800000u) { mode = 2; break; }
            if (v > 1u) mode = 1;
        }
        g_mode = mode;
    }
}

// Merged prep: LUT pack | x pack | misc | 6-bit half tables
#define SEC_LUT  (RNODES * LUT_WORDS)            // 2,097,152
#define SEC_X    (NSAMP * NSTEP)                 // 262,144
#define SEC_MISC (RNODES)                        // 256
#define SEC_T6   (TAB6_ROWS * 128)               // 352,256
#define PREP1_N  (SEC_LUT + SEC_X + SEC_MISC + SEC_T6)

__global__ void prep1_kernel(const int* __restrict__ lut,
                             const void* __restrict__ x,
                             const int* __restrict__ input_nodes,
                             const void* __restrict__ init_res,
                             const void* __restrict__ W,
                             const int* __restrict__ primes) {
    int i = blockIdx.x * blockDim.x + threadIdx.x;
    int mode = g_mode;
    if (i < SEC_LUT) {
        const int* src = lut + (size_t)i * 32;
        uint32_t v = 0;
#pragma unroll
        for (int b = 0; b < 32; b++) v |= ((uint32_t)(src[b] & 1)) << b;
        g_lutbits[i] = v;
        return;
    }
    i -= SEC_LUT;
    if (i < SEC_X) {
        long base = (long)i * 32;
        uint32_t v = 0;
#pragma unroll
        for (int q = 0; q < 32; q++)
            v |= ((uint32_t)read_bool(x, base + q, mode)) << q;
        g_xpack[i] = v;
        return;
    }
    i -= SEC_X;
    if (i < SEC_MISC) {
        int inv = -1;
#pragma unroll
        for (int q = 0; q < NIN; q++)
            if (input_nodes[q] == i) inv = q;
        g_inv[i] = inv;
        g_init[i] = read_bool(init_res, i, mode);
        return;
    }
    i -= SEC_MISC;
    if (i < SEC_T6) {
        // tab6 entry (h, c, t): u16 pair {node t, node t+128} summed over
        // combo bits j of half-group h (k = 6h + j), k < 256 guarded.
        int t = i & 127;
        int c = (i >> 7) & 63;
        int h = i >> 13;
        uint32_t lo = 0, hi = 0;
#pragma unroll
        for (int j = 0; j < 6; j++) {
            int k = 6 * h + j;
            if ((c & (1 << j)) && k < RNODES) {
                uint32_t p = (uint32_t)primes[k];
                if (read_bool(W, (long)t * RNODES + k, mode))         lo += p;
                if (read_bool(W, (long)(t + 128) * RNODES + k, mode)) hi += p;
            }
        }
        g_tab6[i] = lo | (hi << 16);
    }
}

// Build the 12-bit table from two 6-bit halves (memory-bound pass).
__global__ void prep2_kernel() {
    int i = blockIdx.x * blockDim.x + threadIdx.x;
    if (i >= TAB12_ROWS * 128) return;
    int t   = i & 127;
    int row = i >> 7;
    if (row < TAB12_TAIL) {
        int g  = row >> 12;
        int c  = row & 4095;
        int cl = c & 63, ch = c >> 6;
        uint32_t a = g_tab6[((2 * g)     * 64 + cl) * 128 + t];
        uint32_t b = g_tab6[((2 * g + 1) * 64 + ch) * 128 + t];
        g_tab12[i] = __vadd2(a, b);
    } else {
        int c4 = row - TAB12_TAIL;                 // 0..15, k = 252..255
        g_tab12[i] = g_tab6[(42 * 64 + c4) * 128 + t];
    }
}

// 512 CTAs x 128 threads. CTA = one sample; thread t owns nodes t and t+128
// (packed u16 accumulation, spilled every 3 groups).
__global__ void __launch_bounds__(128, 4)
reservoir_kernel(const float* __restrict__ roW,
                 const float* __restrict__ rob,
                 float* __restrict__ out) {
    __shared__ uint32_t sh_xw[NSTEP];
    __shared__ uint32_t sh_r[16];       // 2 bufs * 8 mask words
    __shared__ float    sh_bits[RNODES];

    const int t    = threadIdx.x;       // 0..127
    const int w    = t >> 5;
    const int lane = t & 31;
    const int sid  = blockIdx.x;

    for (int i = t; i < NSTEP; i += 128)
        sh_xw[i] = g_xpack[sid * NSTEP + i];

    const int inv0 = g_inv[t];
    const int inv1 = g_inv[t + 128];
    unsigned b0 = (unsigned)g_init[t];
    unsigned b1 = (unsigned)g_init[t + 128];

    __syncthreads();

    for (int s = 0; s < NSTEP; s++) {
        // 1) input override (before the matvec, as in the reference)
        uint32_t xw = sh_xw[s];
        unsigned a0 = (inv0 >= 0) ? ((xw >> inv0) & 1u) : b0;
        unsigned a1 = (inv1 >= 0) ? ((xw >> inv1) & 1u) : b1;

        // 2) state bitmask words: warp w -> words w and w+4
        unsigned m0 = __ballot_sync(0xffffffffu, a0);
        unsigned m1 = __ballot_sync(0xffffffffu, a1);
        uint32_t* rb = sh_r + (s & 1) * 8;
        if (lane == 0) { rb[w] = m0; rb[w + 4] = m1; }
        __syncthreads();

        uint4 ra  = *(const uint4*)(rb);
        uint4 rb4 = *(const uint4*)(rb + 4);
        uint32_t wv[8] = {ra.x, ra.y, ra.z, ra.w, rb4.x, rb4.y, rb4.z, rb4.w};

        // 3) 12-bit-group combo sums from the 44 MB L2 table:
        //    22 independent coalesced LDG.32, unconditional packed adds.
        uint32_t i0 = 0, i1 = 0;
#pragma unroll
        for (int trip = 0; trip < 7; trip++) {
            uint32_t acc = 0;   // packed u16; 3 groups max 3*19428 < 65536
#pragma unroll
            for (int j = 0; j < 3; j++) {
                int g  = trip * 3 + j;
                int bp = 12 * g;
                int wi = bp >> 5, sh = bp & 31;
                uint32_t c = __funnelshift_r(wv[wi], wv[(wi + 1) & 7], sh) & 0xFFFu;
                acc = __vadd2(acc, g_tab12[((uint32_t)g << 19) + (c << 7) + t]);
            }
            i0 += acc & 0xFFFFu;
            i1 += acc >> 16;
        }
        {   // tail 4-bit group (nodes k=252..255)
            uint32_t c = wv[7] >> 28;
            uint32_t e = g_tab12[((uint32_t)TAB12_TAIL << 7) + (c << 7) + t];
            i0 += e & 0xFFFFu;
            i1 += e >> 16;
        }

        // 4) bit-packed LUT gather (8 MB, L2-resident)
        uint32_t w0 = g_lutbits[((uint32_t)t << 13)         + (i0 >> 5)];
        uint32_t w1 = g_lutbits[((uint32_t)(t + 128) << 13) + (i1 >> 5)];
        b0 = (w0 >> (i0 & 31u)) & 1u;
        b1 = (w1 >> (i1 & 31u)) & 1u;
    }

    // Readout: out[m, o] = sum_j rf[m,j] * roW[o,j] + rob[o]
    sh_bits[t]       = (float)b0;
    sh_bits[t + 128] = (float)b1;
    __syncthreads();

    if (t < NOUT) {
        float acc = rob[t];
        const float* wrow = roW + t * RNODES;
#pragma unroll 8
        for (int j = 0; j < RNODES; j++)
            acc += sh_bits[j] * wrow[j];
        out[sid * NOUT + t] = acc;
    }
}

extern "C" void kernel_launch(void* const* d_in, const int* in_sizes, int n_in,
                              void* d_out, int out_size) {
    const void* x       = d_in[0];                   // bool [512,512,4,8] (dtype-detected)
    const int*  innod   = (const int*)d_in[1];       // int32 [32]
    const int*  lut     = (const int*)d_in[2];       // int32 [256, 262144]
    const void* W       = d_in[3];                   // bool [256,256]
    const int*  primes  = (const int*)d_in[4];       // int32 [256]
    const void* initres = d_in[5];                   // bool [256]
    const float* roW    = (const float*)d_in[6];     // f32 [10,256]
    const float* rob    = (const float*)d_in[7];     // f32 [10]
    float* out = (float*)d_out;                      // f32 [512,10]

    detect_kernel<<<1, 32>>>((const uint32_t*)x);
    prep1_kernel<<<(PREP1_N + 255) / 256, 256>>>(lut, x, innod, initres, W,
                                                 (const int*)d_in[4]);
    prep2_kernel<<<(TAB12_ROWS * 128 + 255) / 256, 256>>>();
    reservoir_kernel<<<NSAMP, 128>>>(roW, rob, out);
}